// round 12
// baseline (speedup 1.0000x reference)
#include <cuda_runtime.h>
#include <cstddef>

#define SDIM 1024
#define BDIM 2
#define CS   768
#define CZ   128
#define HN   24
#define DD   32
#define EPSF 1e-5f
#define NEGINF -1000000000.0f
#define LOG2E 1.4426950408889634f

// ---------------- scratch ----------------
__device__ float g_emb[BDIM * 3 * CS];
__device__ float g_bsn[(size_t)BDIM * SDIM * CS];
__device__ float g_q[(size_t)BDIM * SDIM * CS];
__device__ float g_k[(size_t)BDIM * SDIM * CS];
__device__ float g_v[(size_t)BDIM * SDIM * CS];
__device__ float g_zb[(size_t)HN * SDIM * SDIM];   // (zbias + maskbias) * LOG2E
__device__ float g_att[(size_t)BDIM * SDIM * CS];
__device__ float g_w1[CZ * HN];
__device__ float g_s12[2 * HN];

// ---------------- f32x2 helpers ----------------
typedef unsigned long long u64;
__device__ __forceinline__ u64 ffma2(u64 a, u64 b, u64 c) {
    u64 d; asm("fma.rn.f32x2 %0,%1,%2,%3;" : "=l"(d) : "l"(a), "l"(b), "l"(c)); return d;
}
__device__ __forceinline__ u64 add2(u64 a, u64 b) {
    u64 d; asm("add.rn.f32x2 %0,%1,%2;" : "=l"(d) : "l"(a), "l"(b)); return d;
}
__device__ __forceinline__ u64 pk2(float a, float b) {
    u64 d; asm("mov.b64 %0,{%1,%2};" : "=l"(d) : "f"(a), "f"(b)); return d;
}
__device__ __forceinline__ float2 up2(u64 v) {
    float2 r; asm("mov.b64 {%0,%1},%2;" : "=f"(r.x), "=f"(r.y) : "l"(v)); return r;
}
__device__ __forceinline__ float ex2(float x) {
    float y; asm("ex2.approx.f32 %0, %1;" : "=f"(y) : "f"(x)); return y;
}

// ---------------- 0. zbias prep ----------------
__global__ void zprep_kernel(const float* __restrict__ lnw, const float* __restrict__ lnb,
                             const float* __restrict__ wz) {
    int h = threadIdx.x;
    if (h >= HN) return;
    float s1 = 0.f, s2 = 0.f;
    for (int c = 0; c < CZ; c++) {
        float w1 = lnw[c] * wz[c * HN + h] * LOG2E;
        g_w1[c * HN + h] = w1;
        s1 += w1;
        s2 += lnb[c] * wz[c * HN + h] * LOG2E;
    }
    g_s12[h] = s1;
    g_s12[HN + h] = s2;
}

// ---------------- 1. adaLN ----------------
__global__ void adaln_kernel(const float* __restrict__ t, const float* __restrict__ w,
                             const float* __restrict__ b) {
    __shared__ float st[CS];
    int bb = blockIdx.y;
    for (int c = threadIdx.x; c < CS; c += 256) {
        float x = t[bb * CS + c];
        st[c] = x / (1.f + __expf(-x));
    }
    __syncthreads();
    int n = blockIdx.x * 256 + threadIdx.x;
    float acc = b[n];
#pragma unroll 4
    for (int c = 0; c < CS; c++) acc += st[c] * w[c * 3 * CS + n];
    g_emb[bb * 3 * CS + n] = acc;
}

// ---------------- 2. bs_norm ----------------
__global__ void bsnorm_kernel(const float* __restrict__ bs) {
    int row = blockIdx.x;
    int bb = row >> 10;
    const float* x = bs + (size_t)row * CS;
    float v[3];
    float s = 0.f, s2 = 0.f;
#pragma unroll
    for (int i = 0; i < 3; i++) {
        v[i] = x[threadIdx.x + i * 256];
        s += v[i]; s2 += v[i] * v[i];
    }
    __shared__ float rs[8], rs2[8], mvar[2];
#pragma unroll
    for (int o = 16; o; o >>= 1) {
        s  += __shfl_xor_sync(~0u, s, o);
        s2 += __shfl_xor_sync(~0u, s2, o);
    }
    int lane = threadIdx.x & 31, warp = threadIdx.x >> 5;
    if (lane == 0) { rs[warp] = s; rs2[warp] = s2; }
    __syncthreads();
    if (threadIdx.x == 0) {
        float a = 0.f, c = 0.f;
#pragma unroll
        for (int i = 0; i < 8; i++) { a += rs[i]; c += rs2[i]; }
        float mu = a * (1.f / CS);
        mvar[0] = mu;
        mvar[1] = rsqrtf(c * (1.f / CS) - mu * mu + EPSF);
    }
    __syncthreads();
    float mu = mvar[0], rstd = mvar[1];
    const float* shift = g_emb + bb * 3 * CS;
    const float* scale = shift + CS;
#pragma unroll
    for (int i = 0; i < 3; i++) {
        int c = threadIdx.x + i * 256;
        g_bsn[(size_t)row * CS + c] = (v[i] - mu) * rstd * (1.f + scale[c]) + shift[c];
    }
}

// ---------------- 3. SGEMM v2 (measured best): 128x128, dup-A, occ 2 ----------------
template<int MODE>
__global__ __launch_bounds__(256, 2) void sgemm2(
    const float* __restrict__ A,
    const float* __restrict__ W0, const float* __restrict__ W1, const float* __restrict__ W2,
    float* __restrict__ O0, float* __restrict__ O1, float* __restrict__ O2,
    const float* __restrict__ rq, const float* __restrict__ rk,
    const float* __restrict__ bias) {
    __shared__ float As2[2][8][256];
    __shared__ float Bs[2][8][128];
    int tid = threadIdx.x, tx = tid & 15, ty = tid >> 4;
    int mat, nb;
    const float* B; float* O;
    if (MODE == 0) {
        mat = blockIdx.x / 6; nb = blockIdx.x % 6;
        B = (mat == 0) ? W0 : (mat == 1 ? W1 : W2);
        O = (mat == 0) ? O0 : (mat == 1 ? O1 : O2);
    } else { mat = 0; nb = blockIdx.x; B = W0; O = O0; }
    int m0 = blockIdx.y * 128, n0 = nb * 128;
    const int K = CS, N = CS;
    int arow = tid >> 1, acol = (tid & 1) * 4;
    int brow = tid >> 5, bcol = (tid & 31) * 4;
    const float* Ap = A + (size_t)(m0 + arow) * K + acol;
    const float* Bp = B + (size_t)brow * N + n0 + bcol;

    u64 acc[8][4];
#pragma unroll
    for (int i = 0; i < 8; i++)
#pragma unroll
        for (int j = 0; j < 4; j++) acc[i][j] = 0ULL;

    float4 a4 = *(const float4*)Ap;
    float4 b4 = *(const float4*)Bp;
    {
        float va[4] = {a4.x, a4.y, a4.z, a4.w};
#pragma unroll
        for (int w = 0; w < 4; w++)
            *(float2*)&As2[0][acol + w][2 * arow] = make_float2(va[w], va[w]);
        *(float4*)&Bs[0][brow][bcol] = b4;
    }
    __syncthreads();
    int p = 0;
    for (int kt = 8; ; kt += 8) {
        bool more = kt < K;
        if (more) {
            a4 = *(const float4*)(Ap + kt);
            b4 = *(const float4*)(Bp + (size_t)kt * N);
        }
#pragma unroll
        for (int kk = 0; kk < 8; kk++) {
            const float* ar = &As2[p][kk][ty * 16];
            ulonglong2 aA = *(const ulonglong2*)ar;
            ulonglong2 aB = *(const ulonglong2*)(ar + 4);
            ulonglong2 aC = *(const ulonglong2*)(ar + 8);
            ulonglong2 aD = *(const ulonglong2*)(ar + 12);
            const float* br = &Bs[p][kk][tx * 8];
            ulonglong2 bA = *(const ulonglong2*)br;
            ulonglong2 bB = *(const ulonglong2*)(br + 4);
            u64 av[8] = {aA.x, aA.y, aB.x, aB.y, aC.x, aC.y, aD.x, aD.y};
            u64 bv[4] = {bA.x, bA.y, bB.x, bB.y};
#pragma unroll
            for (int i = 0; i < 8; i++)
#pragma unroll
                for (int j = 0; j < 4; j++) acc[i][j] = ffma2(av[i], bv[j], acc[i][j]);
        }
        if (!more) break;
        {
            float va[4] = {a4.x, a4.y, a4.z, a4.w};
#pragma unroll
            for (int w = 0; w < 4; w++)
                *(float2*)&As2[p ^ 1][acol + w][2 * arow] = make_float2(va[w], va[w]);
            *(float4*)&Bs[p ^ 1][brow][bcol] = b4;
        }
        p ^= 1;
        __syncthreads();
    }

    float vout[8][8];
#pragma unroll
    for (int i = 0; i < 8; i++)
#pragma unroll
        for (int jp = 0; jp < 4; jp++) {
            float2 u = up2(acc[i][jp]);
            vout[i][2 * jp] = u.x; vout[i][2 * jp + 1] = u.y;
        }
    if (MODE == 0 && mat < 2) {
        const float* rw = (mat == 0) ? rq : rk;
        float w8[8];
#pragma unroll
        for (int j = 0; j < 8; j++) w8[j] = rw[(tx * 8 + j) & 31];
#pragma unroll
        for (int i = 0; i < 8; i++) {
            float ss = 0.f;
#pragma unroll
            for (int j = 0; j < 8; j++) ss += vout[i][j] * vout[i][j];
            ss += __shfl_xor_sync(~0u, ss, 1);
            ss += __shfl_xor_sync(~0u, ss, 2);
            float r = rsqrtf(ss * (1.f / DD) + EPSF);
#pragma unroll
            for (int j = 0; j < 8; j++) vout[i][j] *= r * w8[j];
        }
    }
    if (MODE == 1) {
#pragma unroll
        for (int i = 0; i < 8; i++) {
            int mrow = m0 + ty * 8 + i;
            const float* gp = g_emb + (mrow >> 10) * 3 * CS + 2 * CS;
#pragma unroll
            for (int j = 0; j < 8; j++) {
                int n = n0 + tx * 8 + j;
                vout[i][j] = (vout[i][j] + bias[n]) * gp[n];
            }
        }
    }
#pragma unroll
    for (int i = 0; i < 8; i++) {
        size_t off = (size_t)(m0 + ty * 8 + i) * N + n0 + tx * 8;
        *(float4*)&O[off]     = *(float4*)&vout[i][0];
        *(float4*)&O[off + 4] = *(float4*)&vout[i][4];
    }
}

// ---------------- 5. z bias v3: folded-LN GEMM + mask bias folded in ----------------
#define ZJT 512
#define ZKC 8
#define ZPAD 516
__global__ __launch_bounds__(128, 3) void zbias3_kernel(const float* __restrict__ z,
                                                        const int* __restrict__ mask) {
    __shared__ float zts[ZKC * ZPAD];
    __shared__ float w1s[CZ * HN];
    __shared__ float s12s[2 * HN];
    int i = blockIdx.y, j0 = blockIdx.x * ZJT;
    int t = threadIdx.x;

    {
        const float4* w1g4 = (const float4*)g_w1;
        float4* w1s4 = (float4*)w1s;
#pragma unroll
        for (int u = 0; u < 6; u++) w1s4[u * 128 + t] = w1g4[u * 128 + t];
        if (t < 2 * HN) s12s[t] = g_s12[t];
    }

    const float* zp = z + ((size_t)i * SDIM + j0) * CZ;

    u64 acc[4][12];
#pragma unroll
    for (int jj = 0; jj < 4; jj++)
#pragma unroll
        for (int hp = 0; hp < 12; hp++) acc[jj][hp] = 0ULL;
    u64 sum01 = 0ULL, sum23 = 0ULL, sq01 = 0ULL, sq23 = 0ULL;

    float4 pre[8];
#pragma unroll
    for (int l = 0; l < 8; l++) {
        int idx = l * 128 + t;
        int row = idx >> 1, half = idx & 1;
        pre[l] = *(const float4*)(zp + (size_t)row * CZ + half * 4);
    }

    for (int kt = 0; kt < CZ / ZKC; kt++) {
#pragma unroll
        for (int l = 0; l < 8; l++) {
            int idx = l * 128 + t;
            int row = idx >> 1, half = idx & 1;
            float vv[4] = {pre[l].x, pre[l].y, pre[l].z, pre[l].w};
#pragma unroll
            for (int w = 0; w < 4; w++)
                zts[(half * 4 + w) * ZPAD + row] = vv[w];
        }
        __syncthreads();
        if (kt + 1 < CZ / ZKC) {
            int c0 = (kt + 1) * ZKC;
#pragma unroll
            for (int l = 0; l < 8; l++) {
                int idx = l * 128 + t;
                int row = idx >> 1, half = idx & 1;
                pre[l] = *(const float4*)(zp + (size_t)row * CZ + c0 + half * 4);
            }
        }
#pragma unroll
        for (int c = 0; c < ZKC; c++) {
            int cg = kt * ZKC + c;
            float4 zv = *(const float4*)&zts[c * ZPAD + 4 * t];
            u64 z01 = pk2(zv.x, zv.y), z23 = pk2(zv.z, zv.w);
            sum01 = add2(sum01, z01); sum23 = add2(sum23, z23);
            sq01 = ffma2(z01, z01, sq01); sq23 = ffma2(z23, z23, sq23);
            u64 zd[4];
            zd[0] = pk2(zv.x, zv.x); zd[1] = pk2(zv.y, zv.y);
            zd[2] = pk2(zv.z, zv.z); zd[3] = pk2(zv.w, zv.w);
            const ulonglong2* wr = (const ulonglong2*)&w1s[cg * HN];
            ulonglong2 wA = wr[0], wB = wr[1], wC = wr[2];
            ulonglong2 wD = wr[3], wE = wr[4], wF = wr[5];
            u64 wp[12] = {wA.x, wA.y, wB.x, wB.y, wC.x, wC.y,
                          wD.x, wD.y, wE.x, wE.y, wF.x, wF.y};
#pragma unroll
            for (int jj = 0; jj < 4; jj++)
#pragma unroll
                for (int hp = 0; hp < 12; hp++)
                    acc[jj][hp] = ffma2(zd[jj], wp[hp], acc[jj][hp]);
        }
        __syncthreads();
    }

    float2 s01 = up2(sum01), s23 = up2(sum23);
    float2 q01 = up2(sq01), q23 = up2(sq23);
    float S[4] = {s01.x, s01.y, s23.x, s23.y};
    float Q[4] = {q01.x, q01.y, q23.x, q23.y};
    float mu[4], rstd[4];
#pragma unroll
    for (int jj = 0; jj < 4; jj++) {
        mu[jj] = S[jj] * (1.f / CZ);
        rstd[jj] = rsqrtf(Q[jj] * (1.f / CZ) - mu[jj] * mu[jj] + EPSF);
    }
    float mb[4];
    {
        int4 m4 = *(const int4*)(mask + (size_t)i * SDIM + j0 + 4 * t);
        mb[0] = (m4.x > 0) ? 0.f : NEGINF * LOG2E;
        mb[1] = (m4.y > 0) ? 0.f : NEGINF * LOG2E;
        mb[2] = (m4.z > 0) ? 0.f : NEGINF * LOG2E;
        mb[3] = (m4.w > 0) ? 0.f : NEGINF * LOG2E;
    }
#pragma unroll
    for (int hp = 0; hp < 12; hp++) {
        float s1a = s12s[2 * hp], s1b = s12s[2 * hp + 1];
        float s2a = s12s[HN + 2 * hp], s2b = s12s[HN + 2 * hp + 1];
        float oa[4], ob[4];
#pragma unroll
        for (int jj = 0; jj < 4; jj++) {
            float2 a = up2(acc[jj][hp]);
            oa[jj] = rstd[jj] * (a.x - mu[jj] * s1a) + s2a + mb[jj];
            ob[jj] = rstd[jj] * (a.y - mu[jj] * s1b) + s2b + mb[jj];
        }
        size_t base_a = (((size_t)(2 * hp) * SDIM + i) * SDIM) + j0 + 4 * t;
        size_t base_b = (((size_t)(2 * hp + 1) * SDIM + i) * SDIM) + j0 + 4 * t;
        *(float4*)&g_zb[base_a] = make_float4(oa[0], oa[1], oa[2], oa[3]);
        *(float4*)&g_zb[base_b] = make_float4(ob[0], ob[1], ob[2], ob[3]);
    }
}

// ---------------- 7. flash attention v4e: occ 3 (single change vs v4d) ----------------
#define AT_QT  0
#define AT_KT  4224
#define AT_VS  6400
#define AT_PT  8448
#define AT_SMEM_FLOATS 16896   // 67584 bytes; x3 CTAs = 202.8 KB <= 227 KB
__global__ __launch_bounds__(256, 3) void attn4(const float* __restrict__ q,
                                                const float* __restrict__ k,
                                                const float* __restrict__ v,
                                                const float* __restrict__ beta) {
    extern __shared__ float sm[];
    float* QT = sm + AT_QT;
    float* KT = sm + AT_KT;
    float* VS = sm + AT_VS;
    u64*   PT = (u64*)(sm + AT_PT);
    int h = blockIdx.y >> 1, b = blockIdx.y & 1;
    int i0 = blockIdx.x * 128;
    int tid = threadIdx.x, tx = tid & 15, ty = tid >> 4;
    const float sc = 0.17677669529663687f * LOG2E;
    const u64 l2e2 = pk2(LOG2E, LOG2E);

    const float* qp = q + (size_t)b * SDIM * CS + h * DD;
    const float* kp = k + (size_t)b * SDIM * CS + h * DD;
    const float* vp = v + (size_t)b * SDIM * CS + h * DD;
    const float* zbp = g_zb + (size_t)h * SDIM * SDIM;
    const float* btp = beta + (size_t)b * SDIM * SDIM;

#pragma unroll
    for (int l = 0; l < 4; l++) {
        int u = tid + l * 256;
        int r = u >> 3, c4 = u & 7;
        float4 t4 = *(const float4*)(qp + (size_t)(i0 + r) * CS + c4 * 4);
        int d0 = c4 * 4;
        QT[(d0 + 0) * 132 + r] = t4.x * sc;
        QT[(d0 + 1) * 132 + r] = t4.y * sc;
        QT[(d0 + 2) * 132 + r] = t4.z * sc;
        QT[(d0 + 3) * 132 + r] = t4.w * sc;
    }

    u64 acc[4][2];
#pragma unroll
    for (int ip = 0; ip < 4; ip++) { acc[ip][0] = 0ULL; acc[ip][1] = 0ULL; }
    u64 lp2[4] = {0ULL, 0ULL, 0ULL, 0ULL};

    for (int j0 = 0; j0 < SDIM; j0 += 64) {
        float4 kreg[2], vreg[2];
        int ru[2], cu[2];
#pragma unroll
        for (int l = 0; l < 2; l++) {
            int u = tid + l * 256;
            ru[l] = u >> 3; cu[l] = u & 7;
            kreg[l] = *(const float4*)(kp + (size_t)(j0 + ru[l]) * CS + cu[l] * 4);
            vreg[l] = *(const float4*)(vp + (size_t)(j0 + ru[l]) * CS + cu[l] * 4);
        }
        u64 s[4][4];
#pragma unroll
        for (int ip = 0; ip < 4; ip++) {
            int ia = i0 + ty * 8 + 2 * ip, ib = ia + 1;
            size_t roa = (size_t)ia * SDIM + j0 + tx * 4;
            size_t rob = (size_t)ib * SDIM + j0 + tx * 4;
            float4 za = *(const float4*)(zbp + roa);
            float4 zb = *(const float4*)(zbp + rob);
            float4 ba = *(const float4*)(btp + roa);
            float4 bb = *(const float4*)(btp + rob);
            s[ip][0] = ffma2(pk2(ba.x, bb.x), l2e2, pk2(za.x, zb.x));
            s[ip][1] = ffma2(pk2(ba.y, bb.y), l2e2, pk2(za.y, zb.y));
            s[ip][2] = ffma2(pk2(ba.z, bb.z), l2e2, pk2(za.z, zb.z));
            s[ip][3] = ffma2(pk2(ba.w, bb.w), l2e2, pk2(za.w, zb.w));
        }
        __syncthreads();
#pragma unroll
        for (int l = 0; l < 2; l++) {
            int r = ru[l], d0 = cu[l] * 4;
            float kv[4] = {kreg[l].x, kreg[l].y, kreg[l].z, kreg[l].w};
            float vv[4] = {vreg[l].x, vreg[l].y, vreg[l].z, vreg[l].w};
#pragma unroll
            for (int w = 0; w < 4; w++) {
                KT[(d0 + w) * 68 + r] = kv[w];
                VS[r * 32 + d0 + w] = vv[w];
            }
        }
        __syncthreads();

#pragma unroll 8
        for (int kk = 0; kk < DD; kk++) {
            const ulonglong2* qr = (const ulonglong2*)&QT[kk * 132 + ty * 8];
            ulonglong2 qA = qr[0], qB = qr[1];
            float4 kq = *(const float4*)&KT[kk * 68 + tx * 4];
            u64 a[4] = {qA.x, qA.y, qB.x, qB.y};
            u64 bj[4] = {pk2(kq.x, kq.x), pk2(kq.y, kq.y),
                         pk2(kq.z, kq.z), pk2(kq.w, kq.w)};
#pragma unroll
            for (int ip = 0; ip < 4; ip++)
#pragma unroll
                for (int jj = 0; jj < 4; jj++)
                    s[ip][jj] = ffma2(a[ip], bj[jj], s[ip][jj]);
        }

#pragma unroll
        for (int ip = 0; ip < 4; ip++) {
            u64 p[4];
#pragma unroll
            for (int jj = 0; jj < 4; jj++) {
                float2 sv = up2(s[ip][jj]);
                p[jj] = pk2(ex2(sv.x), ex2(sv.y));
            }
            lp2[ip] = add2(lp2[ip], add2(add2(p[0], p[1]), add2(p[2], p[3])));
            int ipg = ty * 4 + ip;
#pragma unroll
            for (int jj = 0; jj < 4; jj++)
                PT[(tx * 4 + jj) * 66 + ipg] = p[jj];
        }
        __syncthreads();

#pragma unroll 8
        for (int kk = 0; kk < 64; kk++) {
            const ulonglong2* pr = (const ulonglong2*)&PT[kk * 66 + ty * 4];
            ulonglong2 pA = pr[0], pB = pr[1];
            float2 v2 = *(const float2*)&VS[kk * 32 + tx * 2];
            u64 vx = pk2(v2.x, v2.x), vy = pk2(v2.y, v2.y);
            u64 p4[4] = {pA.x, pA.y, pB.x, pB.y};
#pragma unroll
            for (int ip = 0; ip < 4; ip++) {
                acc[ip][0] = ffma2(p4[ip], vx, acc[ip][0]);
                acc[ip][1] = ffma2(p4[ip], vy, acc[ip][1]);
            }
        }
    }

    float lpa[4], lpb[4];
#pragma unroll
    for (int ip = 0; ip < 4; ip++) {
        float2 u = up2(lp2[ip]);
        lpa[ip] = u.x; lpb[ip] = u.y;
#pragma unroll
        for (int o = 8; o; o >>= 1) {
            lpa[ip] += __shfl_xor_sync(~0u, lpa[ip], o);
            lpb[ip] += __shfl_xor_sync(~0u, lpb[ip], o);
        }
    }
#pragma unroll
    for (int ip = 0; ip < 4; ip++) {
        float inva = 1.f / lpa[ip], invb = 1.f / lpb[ip];
        float2 d0 = up2(acc[ip][0]);
        float2 d1 = up2(acc[ip][1]);
        int ia = i0 + ty * 8 + 2 * ip;
        size_t oa = ((size_t)b * SDIM + ia) * CS + h * DD + tx * 2;
        *(float2*)&g_att[oa]      = make_float2(d0.x * inva, d1.x * inva);
        *(float2*)&g_att[oa + CS] = make_float2(d0.y * invb, d1.y * invb);
    }
}

// ---------------- launch ----------------
extern "C" void kernel_launch(void* const* d_in, const int* in_sizes, int n_in,
                              void* d_out, int out_size) {
    const float* bs      = (const float*)d_in[0];
    const float* z       = (const float*)d_in[1];
    const float* t       = (const float*)d_in[2];
    const float* beta    = (const float*)d_in[3];
    const int*   z_mask  = (const int*)d_in[4];
    const float* w_adaln = (const float*)d_in[5];
    const float* b_adaln = (const float*)d_in[6];
    const float* ln_z_w  = (const float*)d_in[7];
    const float* ln_z_b  = (const float*)d_in[8];
    const float* w_q     = (const float*)d_in[9];
    const float* w_k     = (const float*)d_in[10];
    const float* w_v     = (const float*)d_in[11];
    const float* w_z     = (const float*)d_in[12];
    const float* rms_q_w = (const float*)d_in[13];
    const float* rms_k_w = (const float*)d_in[14];
    const float* w_o     = (const float*)d_in[15];
    const float* b_o     = (const float*)d_in[16];
    float* out = (float*)d_out;

    float *p_bsn, *p_q, *p_k, *p_v, *p_att;
    cudaGetSymbolAddress((void**)&p_bsn, g_bsn);
    cudaGetSymbolAddress((void**)&p_q,   g_q);
    cudaGetSymbolAddress((void**)&p_k,   g_k);
    cudaGetSymbolAddress((void**)&p_v,   g_v);
    cudaGetSymbolAddress((void**)&p_att, g_att);

    static bool attr_done = false;
    if (!attr_done) {
        cudaFuncSetAttribute(attn4, cudaFuncAttributeMaxDynamicSharedMemorySize,
                             AT_SMEM_FLOATS * 4);
        attr_done = true;
    }

    const int M = BDIM * SDIM;

    zprep_kernel<<<1, 32>>>(ln_z_w, ln_z_b, w_z);
    adaln_kernel<<<dim3(9, BDIM), 256>>>(t, w_adaln, b_adaln);
    bsnorm_kernel<<<M, 256>>>(bs);

    sgemm2<0><<<dim3(18, M / 128), 256>>>(p_bsn, w_q, w_k, w_v, p_q, p_k, p_v,
                                          rms_q_w, rms_k_w, nullptr);

    zbias3_kernel<<<dim3(SDIM / ZJT, SDIM), 128>>>(z, z_mask);

    attn4<<<dim3(SDIM / 128, BDIM * HN), 256, AT_SMEM_FLOATS * 4>>>(p_q, p_k, p_v, beta);

    sgemm2<1><<<dim3(6, M / 128), 256>>>(p_att, w_o, nullptr, nullptr, out, nullptr,
                                         nullptr, nullptr, nullptr, b_o);
}

// round 16
// speedup vs baseline: 1.0438x; 1.0438x over previous
#include <cuda_runtime.h>
#include <cstddef>

#define SDIM 1024
#define BDIM 2
#define CS   768
#define CZ   128
#define HN   24
#define DD   32
#define EPSF 1e-5f
#define NEGINF -1000000000.0f
#define LOG2E 1.4426950408889634f

// ---------------- scratch ----------------
__device__ float g_emb[BDIM * 3 * CS];
__device__ float g_bsn[(size_t)BDIM * SDIM * CS];
__device__ float g_q[(size_t)BDIM * SDIM * CS];
__device__ float g_k[(size_t)BDIM * SDIM * CS];
__device__ float g_v[(size_t)BDIM * SDIM * CS];
__device__ float g_zb[(size_t)HN * SDIM * SDIM];   // (zbias + maskbias) * LOG2E
__device__ float g_att[(size_t)BDIM * SDIM * CS];
__device__ float g_w1[CZ * HN];
__device__ float g_s12[2 * HN];

// ---------------- f32x2 helpers ----------------
typedef unsigned long long u64;
__device__ __forceinline__ u64 ffma2(u64 a, u64 b, u64 c) {
    u64 d; asm("fma.rn.f32x2 %0,%1,%2,%3;" : "=l"(d) : "l"(a), "l"(b), "l"(c)); return d;
}
__device__ __forceinline__ u64 add2(u64 a, u64 b) {
    u64 d; asm("add.rn.f32x2 %0,%1,%2;" : "=l"(d) : "l"(a), "l"(b)); return d;
}
__device__ __forceinline__ u64 pk2(float a, float b) {
    u64 d; asm("mov.b64 %0,{%1,%2};" : "=l"(d) : "f"(a), "f"(b)); return d;
}
__device__ __forceinline__ float2 up2(u64 v) {
    float2 r; asm("mov.b64 {%0,%1},%2;" : "=f"(r.x), "=f"(r.y) : "l"(v)); return r;
}
__device__ __forceinline__ float ex2(float x) {
    float y; asm("ex2.approx.f32 %0, %1;" : "=f"(y) : "f"(x)); return y;
}

// ---------------- 0. zbias prep ----------------
__global__ void zprep_kernel(const float* __restrict__ lnw, const float* __restrict__ lnb,
                             const float* __restrict__ wz) {
    int h = threadIdx.x;
    if (h >= HN) return;
    float s1 = 0.f, s2 = 0.f;
    for (int c = 0; c < CZ; c++) {
        float w1 = lnw[c] * wz[c * HN + h] * LOG2E;
        g_w1[c * HN + h] = w1;
        s1 += w1;
        s2 += lnb[c] * wz[c * HN + h] * LOG2E;
    }
    g_s12[h] = s1;
    g_s12[HN + h] = s2;
}

// ---------------- 1. adaLN ----------------
__global__ void adaln_kernel(const float* __restrict__ t, const float* __restrict__ w,
                             const float* __restrict__ b) {
    __shared__ float st[CS];
    int bb = blockIdx.y;
    for (int c = threadIdx.x; c < CS; c += 256) {
        float x = t[bb * CS + c];
        st[c] = x / (1.f + __expf(-x));
    }
    __syncthreads();
    int n = blockIdx.x * 256 + threadIdx.x;
    float acc = b[n];
#pragma unroll 4
    for (int c = 0; c < CS; c++) acc += st[c] * w[c * 3 * CS + n];
    g_emb[bb * 3 * CS + n] = acc;
}

// ---------------- 2. bs_norm ----------------
__global__ void bsnorm_kernel(const float* __restrict__ bs) {
    int row = blockIdx.x;
    int bb = row >> 10;
    const float* x = bs + (size_t)row * CS;
    float v[3];
    float s = 0.f, s2 = 0.f;
#pragma unroll
    for (int i = 0; i < 3; i++) {
        v[i] = x[threadIdx.x + i * 256];
        s += v[i]; s2 += v[i] * v[i];
    }
    __shared__ float rs[8], rs2[8], mvar[2];
#pragma unroll
    for (int o = 16; o; o >>= 1) {
        s  += __shfl_xor_sync(~0u, s, o);
        s2 += __shfl_xor_sync(~0u, s2, o);
    }
    int lane = threadIdx.x & 31, warp = threadIdx.x >> 5;
    if (lane == 0) { rs[warp] = s; rs2[warp] = s2; }
    __syncthreads();
    if (threadIdx.x == 0) {
        float a = 0.f, c = 0.f;
#pragma unroll
        for (int i = 0; i < 8; i++) { a += rs[i]; c += rs2[i]; }
        float mu = a * (1.f / CS);
        mvar[0] = mu;
        mvar[1] = rsqrtf(c * (1.f / CS) - mu * mu + EPSF);
    }
    __syncthreads();
    float mu = mvar[0], rstd = mvar[1];
    const float* shift = g_emb + bb * 3 * CS;
    const float* scale = shift + CS;
#pragma unroll
    for (int i = 0; i < 3; i++) {
        int c = threadIdx.x + i * 256;
        g_bsn[(size_t)row * CS + c] = (v[i] - mu) * rstd * (1.f + scale[c]) + shift[c];
    }
}

// ---------------- 3. SGEMM v2 (measured best) ----------------
template<int MODE>
__global__ __launch_bounds__(256, 2) void sgemm2(
    const float* __restrict__ A,
    const float* __restrict__ W0, const float* __restrict__ W1, const float* __restrict__ W2,
    float* __restrict__ O0, float* __restrict__ O1, float* __restrict__ O2,
    const float* __restrict__ rq, const float* __restrict__ rk,
    const float* __restrict__ bias) {
    __shared__ float As2[2][8][256];
    __shared__ float Bs[2][8][128];
    int tid = threadIdx.x, tx = tid & 15, ty = tid >> 4;
    int mat, nb;
    const float* B; float* O;
    if (MODE == 0) {
        mat = blockIdx.x / 6; nb = blockIdx.x % 6;
        B = (mat == 0) ? W0 : (mat == 1 ? W1 : W2);
        O = (mat == 0) ? O0 : (mat == 1 ? O1 : O2);
    } else { mat = 0; nb = blockIdx.x; B = W0; O = O0; }
    int m0 = blockIdx.y * 128, n0 = nb * 128;
    const int K = CS, N = CS;
    int arow = tid >> 1, acol = (tid & 1) * 4;
    int brow = tid >> 5, bcol = (tid & 31) * 4;
    const float* Ap = A + (size_t)(m0 + arow) * K + acol;
    const float* Bp = B + (size_t)brow * N + n0 + bcol;

    u64 acc[8][4];
#pragma unroll
    for (int i = 0; i < 8; i++)
#pragma unroll
        for (int j = 0; j < 4; j++) acc[i][j] = 0ULL;

    float4 a4 = *(const float4*)Ap;
    float4 b4 = *(const float4*)Bp;
    {
        float va[4] = {a4.x, a4.y, a4.z, a4.w};
#pragma unroll
        for (int w = 0; w < 4; w++)
            *(float2*)&As2[0][acol + w][2 * arow] = make_float2(va[w], va[w]);
        *(float4*)&Bs[0][brow][bcol] = b4;
    }
    __syncthreads();
    int p = 0;
    for (int kt = 8; ; kt += 8) {
        bool more = kt < K;
        if (more) {
            a4 = *(const float4*)(Ap + kt);
            b4 = *(const float4*)(Bp + (size_t)kt * N);
        }
#pragma unroll
        for (int kk = 0; kk < 8; kk++) {
            const float* ar = &As2[p][kk][ty * 16];
            ulonglong2 aA = *(const ulonglong2*)ar;
            ulonglong2 aB = *(const ulonglong2*)(ar + 4);
            ulonglong2 aC = *(const ulonglong2*)(ar + 8);
            ulonglong2 aD = *(const ulonglong2*)(ar + 12);
            const float* br = &Bs[p][kk][tx * 8];
            ulonglong2 bA = *(const ulonglong2*)br;
            ulonglong2 bB = *(const ulonglong2*)(br + 4);
            u64 av[8] = {aA.x, aA.y, aB.x, aB.y, aC.x, aC.y, aD.x, aD.y};
            u64 bv[4] = {bA.x, bA.y, bB.x, bB.y};
#pragma unroll
            for (int i = 0; i < 8; i++)
#pragma unroll
                for (int j = 0; j < 4; j++) acc[i][j] = ffma2(av[i], bv[j], acc[i][j]);
        }
        if (!more) break;
        {
            float va[4] = {a4.x, a4.y, a4.z, a4.w};
#pragma unroll
            for (int w = 0; w < 4; w++)
                *(float2*)&As2[p ^ 1][acol + w][2 * arow] = make_float2(va[w], va[w]);
            *(float4*)&Bs[p ^ 1][brow][bcol] = b4;
        }
        p ^= 1;
        __syncthreads();
    }

    float vout[8][8];
#pragma unroll
    for (int i = 0; i < 8; i++)
#pragma unroll
        for (int jp = 0; jp < 4; jp++) {
            float2 u = up2(acc[i][jp]);
            vout[i][2 * jp] = u.x; vout[i][2 * jp + 1] = u.y;
        }
    if (MODE == 0 && mat < 2) {
        const float* rw = (mat == 0) ? rq : rk;
        float w8[8];
#pragma unroll
        for (int j = 0; j < 8; j++) w8[j] = rw[(tx * 8 + j) & 31];
#pragma unroll
        for (int i = 0; i < 8; i++) {
            float ss = 0.f;
#pragma unroll
            for (int j = 0; j < 8; j++) ss += vout[i][j] * vout[i][j];
            ss += __shfl_xor_sync(~0u, ss, 1);
            ss += __shfl_xor_sync(~0u, ss, 2);
            float r = rsqrtf(ss * (1.f / DD) + EPSF);
#pragma unroll
            for (int j = 0; j < 8; j++) vout[i][j] *= r * w8[j];
        }
    }
    if (MODE == 1) {
#pragma unroll
        for (int i = 0; i < 8; i++) {
            int mrow = m0 + ty * 8 + i;
            const float* gp = g_emb + (mrow >> 10) * 3 * CS + 2 * CS;
#pragma unroll
            for (int j = 0; j < 8; j++) {
                int n = n0 + tx * 8 + j;
                vout[i][j] = (vout[i][j] + bias[n]) * gp[n];
            }
        }
    }
#pragma unroll
    for (int i = 0; i < 8; i++) {
        size_t off = (size_t)(m0 + ty * 8 + i) * N + n0 + tx * 8;
        *(float4*)&O[off]     = *(float4*)&vout[i][0];
        *(float4*)&O[off + 4] = *(float4*)&vout[i][4];
    }
}

// ---------------- 5. z bias v3: folded-LN GEMM + mask bias folded in ----------------
#define ZJT 512
#define ZKC 8
#define ZPAD 516
__global__ __launch_bounds__(128, 3) void zbias3_kernel(const float* __restrict__ z,
                                                        const int* __restrict__ mask) {
    __shared__ float zts[ZKC * ZPAD];
    __shared__ float w1s[CZ * HN];
    __shared__ float s12s[2 * HN];
    int i = blockIdx.y, j0 = blockIdx.x * ZJT;
    int t = threadIdx.x;

    {
        const float4* w1g4 = (const float4*)g_w1;
        float4* w1s4 = (float4*)w1s;
#pragma unroll
        for (int u = 0; u < 6; u++) w1s4[u * 128 + t] = w1g4[u * 128 + t];
        if (t < 2 * HN) s12s[t] = g_s12[t];
    }

    const float* zp = z + ((size_t)i * SDIM + j0) * CZ;

    u64 acc[4][12];
#pragma unroll
    for (int jj = 0; jj < 4; jj++)
#pragma unroll
        for (int hp = 0; hp < 12; hp++) acc[jj][hp] = 0ULL;
    u64 sum01 = 0ULL, sum23 = 0ULL, sq01 = 0ULL, sq23 = 0ULL;

    float4 pre[8];
#pragma unroll
    for (int l = 0; l < 8; l++) {
        int idx = l * 128 + t;
        int row = idx >> 1, half = idx & 1;
        pre[l] = *(const float4*)(zp + (size_t)row * CZ + half * 4);
    }

    for (int kt = 0; kt < CZ / ZKC; kt++) {
#pragma unroll
        for (int l = 0; l < 8; l++) {
            int idx = l * 128 + t;
            int row = idx >> 1, half = idx & 1;
            float vv[4] = {pre[l].x, pre[l].y, pre[l].z, pre[l].w};
#pragma unroll
            for (int w = 0; w < 4; w++)
                zts[(half * 4 + w) * ZPAD + row] = vv[w];
        }
        __syncthreads();
        if (kt + 1 < CZ / ZKC) {
            int c0 = (kt + 1) * ZKC;
#pragma unroll
            for (int l = 0; l < 8; l++) {
                int idx = l * 128 + t;
                int row = idx >> 1, half = idx & 1;
                pre[l] = *(const float4*)(zp + (size_t)row * CZ + c0 + half * 4);
            }
        }
#pragma unroll
        for (int c = 0; c < ZKC; c++) {
            int cg = kt * ZKC + c;
            float4 zv = *(const float4*)&zts[c * ZPAD + 4 * t];
            u64 z01 = pk2(zv.x, zv.y), z23 = pk2(zv.z, zv.w);
            sum01 = add2(sum01, z01); sum23 = add2(sum23, z23);
            sq01 = ffma2(z01, z01, sq01); sq23 = ffma2(z23, z23, sq23);
            u64 zd[4];
            zd[0] = pk2(zv.x, zv.x); zd[1] = pk2(zv.y, zv.y);
            zd[2] = pk2(zv.z, zv.z); zd[3] = pk2(zv.w, zv.w);
            const ulonglong2* wr = (const ulonglong2*)&w1s[cg * HN];
            ulonglong2 wA = wr[0], wB = wr[1], wC = wr[2];
            ulonglong2 wD = wr[3], wE = wr[4], wF = wr[5];
            u64 wp[12] = {wA.x, wA.y, wB.x, wB.y, wC.x, wC.y,
                          wD.x, wD.y, wE.x, wE.y, wF.x, wF.y};
#pragma unroll
            for (int jj = 0; jj < 4; jj++)
#pragma unroll
                for (int hp = 0; hp < 12; hp++)
                    acc[jj][hp] = ffma2(zd[jj], wp[hp], acc[jj][hp]);
        }
        __syncthreads();
    }

    float2 s01 = up2(sum01), s23 = up2(sum23);
    float2 q01 = up2(sq01), q23 = up2(sq23);
    float S[4] = {s01.x, s01.y, s23.x, s23.y};
    float Q[4] = {q01.x, q01.y, q23.x, q23.y};
    float mu[4], rstd[4];
#pragma unroll
    for (int jj = 0; jj < 4; jj++) {
        mu[jj] = S[jj] * (1.f / CZ);
        rstd[jj] = rsqrtf(Q[jj] * (1.f / CZ) - mu[jj] * mu[jj] + EPSF);
    }
    float mb[4];
    {
        int4 m4 = *(const int4*)(mask + (size_t)i * SDIM + j0 + 4 * t);
        mb[0] = (m4.x > 0) ? 0.f : NEGINF * LOG2E;
        mb[1] = (m4.y > 0) ? 0.f : NEGINF * LOG2E;
        mb[2] = (m4.z > 0) ? 0.f : NEGINF * LOG2E;
        mb[3] = (m4.w > 0) ? 0.f : NEGINF * LOG2E;
    }
#pragma unroll
    for (int hp = 0; hp < 12; hp++) {
        float s1a = s12s[2 * hp], s1b = s12s[2 * hp + 1];
        float s2a = s12s[HN + 2 * hp], s2b = s12s[HN + 2 * hp + 1];
        float oa[4], ob[4];
#pragma unroll
        for (int jj = 0; jj < 4; jj++) {
            float2 a = up2(acc[jj][hp]);
            oa[jj] = rstd[jj] * (a.x - mu[jj] * s1a) + s2a + mb[jj];
            ob[jj] = rstd[jj] * (a.y - mu[jj] * s1b) + s2b + mb[jj];
        }
        size_t base_a = (((size_t)(2 * hp) * SDIM + i) * SDIM) + j0 + 4 * t;
        size_t base_b = (((size_t)(2 * hp + 1) * SDIM + i) * SDIM) + j0 + 4 * t;
        *(float4*)&g_zb[base_a] = make_float4(oa[0], oa[1], oa[2], oa[3]);
        *(float4*)&g_zb[base_b] = make_float4(ob[0], ob[1], ob[2], ob[3]);
    }
}

// ---------------- 7. flash attention v5: 2 barriers/tile, VS double-buffered ----------------
// QT [32][132] @0, KT [32][68] @4224, VS [2][64][32] @6400, PT u64 [64][66] @10496
#define AT_QT  0
#define AT_KT  4224
#define AT_VS  6400
#define AT_PT  10496
#define AT_SMEM_FLOATS 18944   // 75776 bytes -> occ 2
__global__ __launch_bounds__(256, 2) void attn5(const float* __restrict__ q,
                                                const float* __restrict__ k,
                                                const float* __restrict__ v,
                                                const float* __restrict__ beta) {
    extern __shared__ float sm[];
    float* QT  = sm + AT_QT;
    float* KT  = sm + AT_KT;
    float* VS0 = sm + AT_VS;           // two 2048-float buffers
    u64*   PT  = (u64*)(sm + AT_PT);
    int h = blockIdx.y >> 1, b = blockIdx.y & 1;
    int i0 = blockIdx.x * 128;
    int tid = threadIdx.x, tx = tid & 15, ty = tid >> 4;
    const float sc = 0.17677669529663687f * LOG2E;
    const u64 l2e2 = pk2(LOG2E, LOG2E);

    const float* qp = q + (size_t)b * SDIM * CS + h * DD;
    const float* kp = k + (size_t)b * SDIM * CS + h * DD;
    const float* vp = v + (size_t)b * SDIM * CS + h * DD;
    const float* zbp = g_zb + (size_t)h * SDIM * SDIM;
    const float* btp = beta + (size_t)b * SDIM * SDIM;

    int ru[2], cu[2];
#pragma unroll
    for (int l = 0; l < 2; l++) {
        int u = tid + l * 256;
        ru[l] = u >> 3; cu[l] = u & 7;
    }

#pragma unroll
    for (int l = 0; l < 4; l++) {
        int u = tid + l * 256;
        int r = u >> 3, c4 = u & 7;
        float4 t4 = *(const float4*)(qp + (size_t)(i0 + r) * CS + c4 * 4);
        int d0 = c4 * 4;
        QT[(d0 + 0) * 132 + r] = t4.x * sc;
        QT[(d0 + 1) * 132 + r] = t4.y * sc;
        QT[(d0 + 2) * 132 + r] = t4.z * sc;
        QT[(d0 + 3) * 132 + r] = t4.w * sc;
    }
    {
        float4 kreg[2], vreg[2];
#pragma unroll
        for (int l = 0; l < 2; l++) {
            kreg[l] = *(const float4*)(kp + (size_t)ru[l] * CS + cu[l] * 4);
            vreg[l] = *(const float4*)(vp + (size_t)ru[l] * CS + cu[l] * 4);
        }
#pragma unroll
        for (int l = 0; l < 2; l++) {
            int r = ru[l], d0 = cu[l] * 4;
            float kv[4] = {kreg[l].x, kreg[l].y, kreg[l].z, kreg[l].w};
            float vv[4] = {vreg[l].x, vreg[l].y, vreg[l].z, vreg[l].w};
#pragma unroll
            for (int w = 0; w < 4; w++) {
                KT[(d0 + w) * 68 + r] = kv[w];
                VS0[r * 32 + d0 + w] = vv[w];
            }
        }
    }
    __syncthreads();

    u64 acc[4][2];
#pragma unroll
    for (int ip = 0; ip < 4; ip++) { acc[ip][0] = 0ULL; acc[ip][1] = 0ULL; }
    u64 lp2[4] = {0ULL, 0ULL, 0ULL, 0ULL};
    int buf = 0;

    for (int t = 0; t < 16; t++) {
        int j0 = t * 64;
        bool more = t < 15;
        u64 s[4][4];
#pragma unroll
        for (int ip = 0; ip < 4; ip++) {
            int ia = i0 + ty * 8 + 2 * ip, ib = ia + 1;
            size_t roa = (size_t)ia * SDIM + j0 + tx * 4;
            size_t rob = (size_t)ib * SDIM + j0 + tx * 4;
            float4 za = *(const float4*)(zbp + roa);
            float4 zb = *(const float4*)(zbp + rob);
            float4 ba = *(const float4*)(btp + roa);
            float4 bb = *(const float4*)(btp + rob);
            s[ip][0] = ffma2(pk2(ba.x, bb.x), l2e2, pk2(za.x, zb.x));
            s[ip][1] = ffma2(pk2(ba.y, bb.y), l2e2, pk2(za.y, zb.y));
            s[ip][2] = ffma2(pk2(ba.z, bb.z), l2e2, pk2(za.z, zb.z));
            s[ip][3] = ffma2(pk2(ba.w, bb.w), l2e2, pk2(za.w, zb.w));
        }
        float4 kreg[2], vreg[2];
        if (more) {
#pragma unroll
            for (int l = 0; l < 2; l++) {
                kreg[l] = *(const float4*)(kp + (size_t)(j0 + 64 + ru[l]) * CS + cu[l] * 4);
                vreg[l] = *(const float4*)(vp + (size_t)(j0 + 64 + ru[l]) * CS + cu[l] * 4);
            }
        }
#pragma unroll 8
        for (int kk = 0; kk < DD; kk++) {
            const ulonglong2* qr = (const ulonglong2*)&QT[kk * 132 + ty * 8];
            ulonglong2 qA = qr[0], qB = qr[1];
            float4 kq = *(const float4*)&KT[kk * 68 + tx * 4];
            u64 a[4] = {qA.x, qA.y, qB.x, qB.y};
            u64 bj[4] = {pk2(kq.x, kq.x), pk2(kq.y, kq.y),
                         pk2(kq.z, kq.z), pk2(kq.w, kq.w)};
#pragma unroll
            for (int ip = 0; ip < 4; ip++)
#pragma unroll
                for (int jj = 0; jj < 4; jj++)
                    s[ip][jj] = ffma2(a[ip], bj[jj], s[ip][jj]);
        }
#pragma unroll
        for (int ip = 0; ip < 4; ip++) {
            u64 p[4];
#pragma unroll
            for (int jj = 0; jj < 4; jj++) {
                float2 sv = up2(s[ip][jj]);
                p[jj] = pk2(ex2(sv.x), ex2(sv.y));
            }
            lp2[ip] = add2(lp2[ip], add2(add2(p[0], p[1]), add2(p[2], p[3])));
            int ipg = ty * 4 + ip;
#pragma unroll
            for (int jj = 0; jj < 4; jj++)
                PT[(tx * 4 + jj) * 66 + ipg] = p[jj];
        }
        __syncthreads();   // A: PT visible; KT free (all QK done)
        if (more) {
            float* VSn = VS0 + (buf ^ 1) * 2048;
#pragma unroll
            for (int l = 0; l < 2; l++) {
                int r = ru[l], d0 = cu[l] * 4;
                float kv[4] = {kreg[l].x, kreg[l].y, kreg[l].z, kreg[l].w};
                float vv[4] = {vreg[l].x, vreg[l].y, vreg[l].z, vreg[l].w};
#pragma unroll
                for (int w = 0; w < 4; w++) {
                    KT[(d0 + w) * 68 + r] = kv[w];
                    VSn[r * 32 + d0 + w] = vv[w];
                }
            }
        }
        {
            const float* VSc = VS0 + buf * 2048;
#pragma unroll 8
            for (int kk = 0; kk < 64; kk++) {
                const ulonglong2* pr = (const ulonglong2*)&PT[kk * 66 + ty * 4];
                ulonglong2 pA = pr[0], pB = pr[1];
                float2 v2 = *(const float2*)&VSc[kk * 32 + tx * 2];
                u64 vx = pk2(v2.x, v2.x), vy = pk2(v2.y, v2.y);
                u64 p4[4] = {pA.x, pA.y, pB.x, pB.y};
#pragma unroll
                for (int ip = 0; ip < 4; ip++) {
                    acc[ip][0] = ffma2(p4[ip], vx, acc[ip][0]);
                    acc[ip][1] = ffma2(p4[ip], vy, acc[ip][1]);
                }
            }
        }
        if (more) __syncthreads();   // B: PV done, new KT/VS visible
        buf ^= 1;
    }

    float lpa[4], lpb[4];
#pragma unroll
    for (int ip = 0; ip < 4; ip++) {
        float2 u = up2(lp2[ip]);
        lpa[ip] = u.x; lpb[ip] = u.y;
#pragma unroll
        for (int o = 8; o; o >>= 1) {
            lpa[ip] += __shfl_xor_sync(~0u, lpa[ip], o);
            lpb[ip] += __shfl_xor_sync(~0u, lpb[ip], o);
        }
    }
#pragma unroll
    for (int ip = 0; ip < 4; ip++) {
        float inva = 1.f / lpa[ip], invb = 1.f / lpb[ip];
        float2 d0 = up2(acc[ip][0]);
        float2 d1 = up2(acc[ip][1]);
        int ia = i0 + ty * 8 + 2 * ip;
        size_t oa = ((size_t)b * SDIM + ia) * CS + h * DD + tx * 2;
        *(float2*)&g_att[oa]      = make_float2(d0.x * inva, d1.x * inva);
        *(float2*)&g_att[oa + CS] = make_float2(d0.y * invb, d1.y * invb);
    }
}

// ---------------- launch ----------------
extern "C" void kernel_launch(void* const* d_in, const int* in_sizes, int n_in,
                              void* d_out, int out_size) {
    const float* bs      = (const float*)d_in[0];
    const float* z       = (const float*)d_in[1];
    const float* t       = (const float*)d_in[2];
    const float* beta    = (const float*)d_in[3];
    const int*   z_mask  = (const int*)d_in[4];
    const float* w_adaln = (const float*)d_in[5];
    const float* b_adaln = (const float*)d_in[6];
    const float* ln_z_w  = (const float*)d_in[7];
    const float* ln_z_b  = (const float*)d_in[8];
    const float* w_q     = (const float*)d_in[9];
    const float* w_k     = (const float*)d_in[10];
    const float* w_v     = (const float*)d_in[11];
    const float* w_z     = (const float*)d_in[12];
    const float* rms_q_w = (const float*)d_in[13];
    const float* rms_k_w = (const float*)d_in[14];
    const float* w_o     = (const float*)d_in[15];
    const float* b_o     = (const float*)d_in[16];
    float* out = (float*)d_out;

    float *p_bsn, *p_q, *p_k, *p_v, *p_att;
    cudaGetSymbolAddress((void**)&p_bsn, g_bsn);
    cudaGetSymbolAddress((void**)&p_q,   g_q);
    cudaGetSymbolAddress((void**)&p_k,   g_k);
    cudaGetSymbolAddress((void**)&p_v,   g_v);
    cudaGetSymbolAddress((void**)&p_att, g_att);

    static bool attr_done = false;
    if (!attr_done) {
        cudaFuncSetAttribute(attn5, cudaFuncAttributeMaxDynamicSharedMemorySize,
                             AT_SMEM_FLOATS * 4);
        attr_done = true;
    }

    const int M = BDIM * SDIM;

    zprep_kernel<<<1, 32>>>(ln_z_w, ln_z_b, w_z);
    adaln_kernel<<<dim3(9, BDIM), 256>>>(t, w_adaln, b_adaln);
    bsnorm_kernel<<<M, 256>>>(bs);

    sgemm2<0><<<dim3(18, M / 128), 256>>>(p_bsn, w_q, w_k, w_v, p_q, p_k, p_v,
                                          rms_q_w, rms_k_w, nullptr);

    zbias3_kernel<<<dim3(SDIM / ZJT, SDIM), 128>>>(z, z_mask);

    attn5<<<dim3(SDIM / 128, BDIM * HN), 256, AT_SMEM_FLOATS * 4>>>(p_q, p_k, p_v, beta);

    sgemm2<1><<<dim3(6, M / 128), 256>>>(p_att, w_o, nullptr, nullptr, out, nullptr,
                                         nullptr, nullptr, nullptr, b_o);
}